// round 15
// baseline (speedup 1.0000x reference)
#include <cuda_runtime.h>
#include <cuda_bf16.h>

// loss = -(1/B) * sum_b [ 1 / (sum_j sigmoid(x[b,j] - x[b,0]) + 0.5) ]
// B = 32, N = 2048. Only row i=0 of the reference's [B,N,N] pair matrix is
// used, so compute the O(B*N) reduction directly.
//
// R14 post-mortem: grid=32 was MUFU-throughput-bound (4096 MUFU ops/SM =
// 8192 cyc = the measured 4.6us). Fix: spread over 128 blocks (32 rows x 4
// chunks) -> 1024 MUFU ops/SM (~1.1us), recombine chunks per row with a
// packed u64 atomic, keep the PDL init-overlap + fire-and-forget final add.
//
//  - node A (PDL trigger): zeroes out[0] every replay.
//  - node B: 128 blocks x 128 threads, 1 float4/thread. Per-thread sigmoid
//    sum quantized at 2^21 (sigmoid>0 -> no bias; block sum <= 2^30, int32
//    safe), redux.sync.add.s32 warp reduce, smem combine of 4 warps.
//  - row combine: atomicAdd(&g_row[row], (1<<40)|sum). The chunk seeing
//    count==3 in the RETURN VALUE owns the full row sum: computes
//    rr = 1/(t+0.5), resets g_row[row] (all chunks arrived -> no race;
//    state back to 0 every launch -> graph-replay safe), then
//    cudaGridDependencySynchronize() + atomicAdd(out, -rr/32) whose return
//    is unused -> REDG fire-and-forget.

#define RB      32
#define CHUNKS  4                 /* blocks per row */
#define ROW_SHIFT 40
#define ROW_MASK  ((1ULL << ROW_SHIFT) - 1ULL)
#define TQ_SCALE  2097152.0f      /* 2^21 */
#define TQ_INV    (1.0f / 2097152.0f)

static __device__ unsigned long long g_row[RB];  // zero-init; reset per launch

static __global__ void rankloss_init(float* __restrict__ out) {
    out[0] = 0.0f;
    __threadfence();
    cudaTriggerProgrammaticLaunchCompletion();
}

static __global__ void __launch_bounds__(128) rankloss_main(
    const float* __restrict__ x, float* __restrict__ out, float inv_B)
{
    const int bx    = blockIdx.x;
    const int row   = bx >> 2;        // 32 rows
    const int chunk = bx & 3;         // 4 chunks of 512 elements
    const int tid   = threadIdx.x;

    const float* rp = x + (size_t)row * 2048;
    const float x0 = __ldg(rp);

    // chunk covers elements [chunk*512, chunk*512+512) = 128 float4.
    const float4* r4 = reinterpret_cast<const float4*>(rp);
    float4 v = __ldg(r4 + (chunk << 7) + tid);

    // sigmoid(v - x0) = 1 / (1 + exp(x0 - v)); s in (0, 4].
    float s = 0.0f;
    s += __fdividef(1.0f, 1.0f + __expf(x0 - v.x));
    s += __fdividef(1.0f, 1.0f + __expf(x0 - v.y));
    s += __fdividef(1.0f, 1.0f + __expf(x0 - v.z));
    s += __fdividef(1.0f, 1.0f + __expf(x0 - v.w));

    // Quantize (si <= 2^23; warp sum <= 2^28; block sum <= 2^30: int32 safe),
    // one-instruction warp reduce.
    int si = __float2int_rn(s * TQ_SCALE);
    int w  = __reduce_add_sync(0xFFFFFFFFu, si);

    __shared__ int warp_sums[4];
    const int warp = tid >> 5;
    const int lane = tid & 31;
    if (lane == 0) warp_sums[warp] = w;
    __syncthreads();

    if (tid == 0) {
        int bsum = warp_sums[0] + warp_sums[1] + warp_sums[2] + warp_sums[3];

        // Packed row atomic: arrival count at bit 40, sum (always >= 0,
        // accumulates to <= 2^32) in the low field.
        unsigned long long contrib =
            (1ULL << ROW_SHIFT) | (unsigned long long)(unsigned int)bsum;
        unsigned long long old = atomicAdd(&g_row[row], contrib);

        if ((old >> ROW_SHIFT) == (unsigned long long)(CHUNKS - 1)) {
            // Row winner: full row sum from the return value.
            unsigned long long tq =
                (old & ROW_MASK) + (unsigned long long)(unsigned int)bsum;
            float t = (float)(long long)tq * TQ_INV;     // sum_j sigmoid
            float part = -(1.0f / (t + 0.5f)) * inv_B;   // -rr/32

            // Reset this row's accumulator for the next replay (all 4 chunks
            // have arrived -> no race).
            asm volatile("st.relaxed.gpu.global.u64 [%0], %1;"
                         :: "l"(&g_row[row]), "l"(0ULL) : "memory");

            // Wait for node A's zero (PDL: usually already done), then
            // fire-and-forget accumulate (return unused -> REDG, no stall).
            cudaGridDependencySynchronize();
            atomicAdd(out, part);
        }
    }
}

extern "C" void kernel_launch(void* const* d_in, const int* in_sizes, int n_in,
                              void* d_out, int out_size) {
    const float* x = (const float*)d_in[0];
    float* out = (float*)d_out;

    const int total = in_sizes[0];   // B * N = 65536
    const int N = 2048;
    const int B = total / N;         // 32 == RB

    rankloss_init<<<1, 1>>>(out);

    cudaLaunchConfig_t cfg = {};
    cfg.gridDim  = dim3((unsigned)(B * CHUNKS), 1, 1);
    cfg.blockDim = dim3(128, 1, 1);
    cfg.dynamicSmemBytes = 0;
    cfg.stream = 0;
    cudaLaunchAttribute attr[1];
    attr[0].id = cudaLaunchAttributeProgrammaticStreamSerialization;
    attr[0].val.programmaticStreamSerializationAllowed = 1;
    cfg.attrs = attr;
    cfg.numAttrs = 1;

    float inv_B = 1.0f / (float)B;
    cudaLaunchKernelEx(&cfg, rankloss_main, x, out, inv_B);
}

// round 16
// speedup vs baseline: 1.0435x; 1.0435x over previous
#include <cuda_runtime.h>
#include <cuda_bf16.h>

// loss = -(1/B) * sum_b [ 1 / (sum_j sigmoid(x[b,j] - x[b,0]) + 0.5) ]
// B = 32, N = 2048. Only row i=0 of the reference's [B,N,N] pair matrix is
// used, so compute the O(B*N) reduction directly.
//
// Evidence through R15: kernel duration is launch-overhead dominated
// (~4.5us regardless of per-SM work); the controllable term is the last
// warp's serial chain. This round: R14's structure (best kernel dur, 4.61us)
// with a halved per-warp chain.
//
//  - node A zeroes out[0], fences, triggers programmatic launch completion
//    (re-zeroed every replay -> graph-replay safe).
//  - node B (ProgrammaticStreamSerialization): 32 blocks x 512 threads,
//    ONE float4 per thread (4-sigmoid chain instead of 8), per-thread sum
//    quantized at 2^19 (block worst case 2^30 -> int32-safe),
//    redux.sync.add.s32 warp reduce (redux.f32 illegal on sm_103),
//    smem[16] + one bar, then warp 0 redux-combines the 16 warp sums in one
//    instruction. tid 0: gridsync (init is ~instant) + fire-and-forget
//    atomicAdd(out, part) — return unused -> REDG, no ATOMG-return wait.

#define RB 32
#define TQ_SCALE 524288.0f        /* 2^19 */
#define TQ_INV   (1.0f / 524288.0f)

static __global__ void rankloss_init(float* __restrict__ out) {
    out[0] = 0.0f;
    __threadfence();
    cudaTriggerProgrammaticLaunchCompletion();
}

static __global__ void __launch_bounds__(512) rankloss_main(
    const float* __restrict__ x, float* __restrict__ out, float inv_B)
{
    const int b   = blockIdx.x;
    const int tid = threadIdx.x;
    const float* row = x + (size_t)b * 2048;

    const float x0 = __ldg(row);

    // 2048 floats = 512 float4; 512 threads -> exactly one load each.
    const float4* row4 = reinterpret_cast<const float4*>(row);
    float4 v = __ldg(row4 + tid);

    // sigmoid(v - x0) = 1 / (1 + exp(x0 - v)); two accumulators.
    float s0, s1;
    s0 = __fdividef(1.0f, 1.0f + __expf(x0 - v.x));
    s1 = __fdividef(1.0f, 1.0f + __expf(x0 - v.y));
    s0 += __fdividef(1.0f, 1.0f + __expf(x0 - v.z));
    s1 += __fdividef(1.0f, 1.0f + __expf(x0 - v.w));
    float s = s0 + s1;  // in (0, 4]

    // Quantize (si <= 2^21, warp sum <= 2^26, block sum <= 2^30: int32-safe),
    // one-instruction warp reduce.
    int si = __float2int_rn(s * TQ_SCALE);
    int w  = __reduce_add_sync(0xFFFFFFFFu, si);

    __shared__ int warp_sums[16];
    const int warp = tid >> 5;
    const int lane = tid & 31;
    if (lane == 0) warp_sums[warp] = w;
    __syncthreads();

    if (warp == 0) {
        // One more redux over the 16 warp sums (lanes 16-31 contribute 0).
        int v16 = (lane < 16) ? warp_sums[lane] : 0;
        int ti  = __reduce_add_sync(0xFFFFFFFFu, v16);

        if (lane == 0) {
            float t = (float)ti * TQ_INV;               // row sum
            float part = -(1.0f / (t + 0.5f)) * inv_B;  // -rr/32

            // PDL: wait for node A's zero (normally already satisfied),
            // then fire-and-forget accumulate (return unused -> REDG).
            cudaGridDependencySynchronize();
            atomicAdd(out, part);
        }
    }
}

extern "C" void kernel_launch(void* const* d_in, const int* in_sizes, int n_in,
                              void* d_out, int out_size) {
    const float* x = (const float*)d_in[0];
    float* out = (float*)d_out;

    const int total = in_sizes[0];   // B * N = 65536
    const int N = 2048;
    const int B = total / N;         // 32 == RB

    rankloss_init<<<1, 1>>>(out);

    cudaLaunchConfig_t cfg = {};
    cfg.gridDim  = dim3((unsigned)B, 1, 1);
    cfg.blockDim = dim3(512, 1, 1);
    cfg.dynamicSmemBytes = 0;
    cfg.stream = 0;  // legacy default stream, same as <<<>>> above
    cudaLaunchAttribute attr[1];
    attr[0].id = cudaLaunchAttributeProgrammaticStreamSerialization;
    attr[0].val.programmaticStreamSerializationAllowed = 1;
    cfg.attrs = attr;
    cfg.numAttrs = 1;

    float inv_B = 1.0f / (float)B;
    cudaLaunchKernelEx(&cfg, rankloss_main, x, out, inv_B);
}